// round 11
// baseline (speedup 1.0000x reference)
#include <cuda_runtime.h>
#include <math.h>
#include <stdint.h>

#define BB 2
#define SS 2048
#define DD 1024
#define HH 16
#define HD 64

// -------- scratch (allocation-free: __device__ globals) --------
__device__ float g_Q[BB*SS*DD];
__device__ float g_K[BB*SS*DD];
__device__ float g_V[BB*SS*DD];
__device__ float g_att[BB*SS*DD];

// -------- helpers --------
__device__ __forceinline__ uint32_t f2tf32(float x) {
    uint32_t r;
    asm("cvt.rna.tf32.f32 %0, %1;" : "=r"(r) : "f"(x));
    return r;
}

__device__ __forceinline__ void mma_tf32(float* d, const uint32_t* a, const uint32_t* b) {
    asm volatile(
        "mma.sync.aligned.m16n8k8.row.col.f32.tf32.tf32.f32 "
        "{%0,%1,%2,%3},{%4,%5,%6,%7},{%8,%9},{%0,%1,%2,%3};"
        : "+f"(d[0]), "+f"(d[1]), "+f"(d[2]), "+f"(d[3])
        : "r"(a[0]), "r"(a[1]), "r"(a[2]), "r"(a[3]), "r"(b[0]), "r"(b[1]));
}

__device__ __forceinline__ void cp_async16(uint32_t smem_addr, const void* gptr) {
    asm volatile("cp.async.cg.shared.global [%0], [%1], 16;"
                 :: "r"(smem_addr), "l"(gptr));
}
__device__ __forceinline__ void cp_commit() {
    asm volatile("cp.async.commit_group;");
}
template <int N>
__device__ __forceinline__ void cp_wait() {
    asm volatile("cp.async.wait_group %0;" :: "n"(N));
}

// ======================================================================
// GEMM (R5-proven config): C = A * Bw^T (+bias), tf32 mma.sync.
// block 128M x 256N, 256 threads (8 warps, 2Mx4N), warp tile 64x64, KT=32
// 2-stage cp.async (110KB smem -> 2 CTAs/SM). round_out rounds scratch.
// ======================================================================
#define G_SMEM_BYTES ((2*128*36 + 2*256*36) * 4)

__device__ __forceinline__ void gemm_body(
    const float* __restrict__ A, const float* __restrict__ Bw,
    const float* __restrict__ bias, float* __restrict__ C, int round_out)
{
    extern __shared__ float gsm[];
    float* As = gsm;                 // [2][128*36]
    float* Bs = gsm + 2 * 128 * 36;  // [2][256*36]

    const int tid  = threadIdx.x;
    const int lane = tid & 31;
    const int w    = tid >> 5;
    const int wm   = w & 1;
    const int wn   = w >> 1;
    const int lr   = lane >> 2;
    const int lc   = lane & 3;

    const int m0 = blockIdx.y * 128;
    const int n0 = blockIdx.x * 256;
    const int K = 1024, N = 1024;

    const uint32_t as_base = (uint32_t)__cvta_generic_to_shared(As);
    const uint32_t bs_base = (uint32_t)__cvta_generic_to_shared(Bs);

    auto load_stage = [&](int s, int kt) {
        #pragma unroll
        for (int i = 0; i < 4; i++) {
            int id = tid + i * 256;
            int r = id >> 3, c = (id & 7) * 4;
            cp_async16(as_base + (s * 128 * 36 + r * 36 + c) * 4,
                       &A[(size_t)(m0 + r) * K + kt + c]);
        }
        #pragma unroll
        for (int i = 0; i < 8; i++) {
            int id = tid + i * 256;
            int r = id >> 3, c = (id & 7) * 4;
            cp_async16(bs_base + (s * 256 * 36 + r * 36 + c) * 4,
                       &Bw[(size_t)(n0 + r) * K + kt + c]);
        }
        cp_commit();
    };

    float acc[4][8][4];
    #pragma unroll
    for (int i = 0; i < 4; i++)
        #pragma unroll
        for (int j = 0; j < 8; j++)
            #pragma unroll
            for (int t = 0; t < 4; t++) acc[i][j][t] = 0.0f;

    load_stage(0, 0);

    int st = 0;
    for (int kt = 0; kt < K; kt += 32, st ^= 1) {
        if (kt + 32 < K) { load_stage(st ^ 1, kt + 32); cp_wait<1>(); }
        else             { cp_wait<0>(); }
        __syncthreads();

        const float* Ac = As + st * 128 * 36;
        const float* Bc = Bs + st * 256 * 36;

        #pragma unroll
        for (int ks = 0; ks < 4; ks++) {
            const int kk = ks * 8;
            uint32_t af[4][4];
            #pragma unroll
            for (int mf = 0; mf < 4; mf++) {
                int r = wm * 64 + mf * 16 + lr;
                af[mf][0] = f2tf32(Ac[r * 36 + kk + lc]);
                af[mf][1] = f2tf32(Ac[(r + 8) * 36 + kk + lc]);
                af[mf][2] = f2tf32(Ac[r * 36 + kk + lc + 4]);
                af[mf][3] = f2tf32(Ac[(r + 8) * 36 + kk + lc + 4]);
            }
            uint32_t bf[8][2];
            #pragma unroll
            for (int nf = 0; nf < 8; nf++) {
                int n = wn * 64 + nf * 8 + lr;
                bf[nf][0] = f2tf32(Bc[n * 36 + kk + lc]);
                bf[nf][1] = f2tf32(Bc[n * 36 + kk + lc + 4]);
            }
            #pragma unroll
            for (int mf = 0; mf < 4; mf++)
                #pragma unroll
                for (int nf = 0; nf < 8; nf++)
                    mma_tf32(acc[mf][nf], af[mf], bf[nf]);
        }
        __syncthreads();
    }

    #pragma unroll
    for (int mf = 0; mf < 4; mf++) {
        int r = m0 + wm * 64 + mf * 16 + lr;
        #pragma unroll
        for (int nf = 0; nf < 8; nf++) {
            int c = n0 + wn * 64 + nf * 8 + 2 * lc;
            float b0 = 0.0f, b1 = 0.0f;
            if (bias) { b0 = bias[c]; b1 = bias[c + 1]; }
            float o00 = acc[mf][nf][0] + b0, o01 = acc[mf][nf][1] + b1;
            float o10 = acc[mf][nf][2] + b0, o11 = acc[mf][nf][3] + b1;
            if (round_out) {
                o00 = __uint_as_float(f2tf32(o00)); o01 = __uint_as_float(f2tf32(o01));
                o10 = __uint_as_float(f2tf32(o10)); o11 = __uint_as_float(f2tf32(o11));
            }
            float2 v0 = { o00, o01 };
            float2 v1 = { o10, o11 };
            *(float2*)&C[(size_t)r * N + c] = v0;
            *(float2*)&C[(size_t)(r + 8) * N + c] = v1;
        }
    }
}

__global__ __launch_bounds__(256) void gemm_qkv(
    const float* __restrict__ Xq, const float* __restrict__ Xk,
    const float* __restrict__ Xv,
    const float* __restrict__ Wq, const float* __restrict__ Wk,
    const float* __restrict__ Wv,
    float* __restrict__ Oq, float* __restrict__ Ok, float* __restrict__ Ov)
{
    const int z = blockIdx.z;
    const float* A  = (z == 0) ? Xq : (z == 1) ? Xk : Xv;
    const float* Bw = (z == 0) ? Wq : (z == 1) ? Wk : Wv;
    float*       C  = (z == 0) ? Oq : (z == 1) ? Ok : Ov;
    gemm_body(A, Bw, nullptr, C, 1);
}

__global__ __launch_bounds__(256) void gemm_out(
    const float* __restrict__ A, const float* __restrict__ Bw,
    const float* __restrict__ bias, float* __restrict__ C)
{
    gemm_body(A, Bw, bias, C, 0);
}

// ======================================================================
// Flash attention v5: 128-q tile, 4 warps (32q each), 32-key tiles,
// cp.async K/V fills, 3 CTAs/SM (smem 69KB, regs capped via launch_bounds).
// Inputs pre-rounded tf32 by gemm epilogue -> no cvt on Q/K/V.
// smem floats: qs 128x68 @0, ks 32x68 @8704, vs 32x68 @10880,
//              ps 128x36 @13056  -> total 17664 floats = 70,656 B
// ======================================================================
#define FL_STR 68
#define PS_STR 36
#define FL_SMEM_BYTES (17664 * 4)

__global__ __launch_bounds__(128, 3) void flash_tf32_v5(
    const float* __restrict__ Q, const float* __restrict__ Kp,
    const float* __restrict__ Vp, float* __restrict__ O)
{
    extern __shared__ float smf[];
    uint32_t* qs = (uint32_t*)smf;
    uint32_t* ks = (uint32_t*)(smf + 8704);
    uint32_t* vs = (uint32_t*)(smf + 10880);
    uint32_t* ps = (uint32_t*)(smf + 13056);

    const int tid  = threadIdx.x;
    const int lane = tid & 31;
    const int w    = tid >> 5;
    const int lr   = lane >> 2;
    const int lc   = lane & 3;

    const int bh = blockIdx.y;
    const int b  = bh >> 4;
    const int h  = bh & 15;
    const int q0 = blockIdx.x * 128;
    const float scale = 0.03125f;   // 2^-5 exact

    const int fr = tid >> 4;          // 0..7
    const int fc = (tid & 15) * 4;    // 0..60

    // ---- load Q tile (128x64), exact scale, raw tf32 bits ----
    const float* qbase = Q + ((size_t)(b * SS + q0)) * DD + h * HD;
    #pragma unroll
    for (int i = 0; i < 16; i++) {
        int r = fr + i * 8;
        float4 v = *(const float4*)&qbase[(size_t)r * DD + fc];
        uint4 u = { __float_as_uint(v.x * scale), __float_as_uint(v.y * scale),
                    __float_as_uint(v.z * scale), __float_as_uint(v.w * scale) };
        *(uint4*)&qs[r * FL_STR + fc] = u;
    }

    float m_state[2][2], l_state[2][2];
    float acco[2][8][4];
    #pragma unroll
    for (int mf = 0; mf < 2; mf++)
        #pragma unroll
        for (int hh = 0; hh < 2; hh++) { m_state[mf][hh] = -INFINITY; l_state[mf][hh] = 0.0f; }
    #pragma unroll
    for (int mf = 0; mf < 2; mf++)
        #pragma unroll
        for (int nf = 0; nf < 8; nf++)
            #pragma unroll
            for (int t = 0; t < 4; t++) acco[mf][nf][t] = 0.0f;

    const uint32_t ks_base = (uint32_t)__cvta_generic_to_shared(ks);
    const uint32_t vs_base = (uint32_t)__cvta_generic_to_shared(vs);

    // fill mapping: 32 rows x 16 chunks = 512 chunks, 128 threads x 4
    const int gr = tid >> 2;            // 0..31 row
    const int gc = (tid & 3) * 16;      // 0..48 col (float)

    for (int kb = 0; kb < SS / 32; kb++) {
        __syncthreads();   // previous tile fully consumed
        {
            const float* kbase = Kp + ((size_t)(b * SS + kb * 32)) * DD + h * HD;
            const float* vbase = Vp + ((size_t)(b * SS + kb * 32)) * DD + h * HD;
            #pragma unroll
            for (int i = 0; i < 4; i++) {
                int c = gc + i * 4;
                cp_async16(ks_base + (gr * FL_STR + c) * 4, &kbase[(size_t)gr * DD + c]);
                cp_async16(vs_base + (gr * FL_STR + c) * 4, &vbase[(size_t)gr * DD + c]);
            }
            cp_commit();
            cp_wait<0>();
        }
        __syncthreads();   // tile visible

        // ---- S = Q K^T : warp tile 32q x 32keys ----
        float accs[2][4][4];
        #pragma unroll
        for (int mf = 0; mf < 2; mf++)
            #pragma unroll
            for (int nf = 0; nf < 4; nf++)
                #pragma unroll
                for (int t = 0; t < 4; t++) accs[mf][nf][t] = 0.0f;

        #pragma unroll
        for (int ksi = 0; ksi < 8; ksi++) {
            const int kk = ksi * 8;
            uint32_t af[2][4];
            #pragma unroll
            for (int mf = 0; mf < 2; mf++) {
                int r = w * 32 + mf * 16 + lr;
                af[mf][0] = qs[r * FL_STR + kk + lc];
                af[mf][1] = qs[(r + 8) * FL_STR + kk + lc];
                af[mf][2] = qs[r * FL_STR + kk + lc + 4];
                af[mf][3] = qs[(r + 8) * FL_STR + kk + lc + 4];
            }
            uint32_t bf[4][2];
            #pragma unroll
            for (int nf = 0; nf < 4; nf++) {
                int n = nf * 8 + lr;
                bf[nf][0] = ks[n * FL_STR + kk + lc];
                bf[nf][1] = ks[n * FL_STR + kk + lc + 4];
            }
            #pragma unroll
            for (int mf = 0; mf < 2; mf++)
                #pragma unroll
                for (int nf = 0; nf < 4; nf++)
                    mma_tf32(accs[mf][nf], af[mf], bf[nf]);
        }

        // ---- warp-local online softmax ----
        float cc[2][2];
        #pragma unroll
        for (int mf = 0; mf < 2; mf++)
            #pragma unroll
            for (int hh = 0; hh < 2; hh++) {
                float v = -INFINITY;
                #pragma unroll
                for (int nf = 0; nf < 4; nf++) {
                    v = fmaxf(v, accs[mf][nf][2 * hh]);
                    v = fmaxf(v, accs[mf][nf][2 * hh + 1]);
                }
                v = fmaxf(v, __shfl_xor_sync(0xffffffffu, v, 1));
                v = fmaxf(v, __shfl_xor_sync(0xffffffffu, v, 2));
                float mnew = fmaxf(m_state[mf][hh], v);
                cc[mf][hh] = __expf(m_state[mf][hh] - mnew);
                m_state[mf][hh] = mnew;
            }

        float rsum[2][2] = {};
        #pragma unroll
        for (int mf = 0; mf < 2; mf++) {
            #pragma unroll
            for (int nf = 0; nf < 4; nf++) {
                float p0 = __expf(accs[mf][nf][0] - m_state[mf][0]);
                float p1 = __expf(accs[mf][nf][1] - m_state[mf][0]);
                float p2 = __expf(accs[mf][nf][2] - m_state[mf][1]);
                float p3 = __expf(accs[mf][nf][3] - m_state[mf][1]);
                rsum[mf][0] += p0 + p1;
                rsum[mf][1] += p2 + p3;
                int r = w * 32 + mf * 16 + lr;
                int c = nf * 8 + 2 * lc;
                uint2 u0 = { f2tf32(p0), f2tf32(p1) };
                uint2 u1 = { f2tf32(p2), f2tf32(p3) };
                *(uint2*)&ps[r * PS_STR + c] = u0;
                *(uint2*)&ps[(r + 8) * PS_STR + c] = u1;
            }
        }
        #pragma unroll
        for (int mf = 0; mf < 2; mf++)
            #pragma unroll
            for (int hh = 0; hh < 2; hh++) {
                float v = rsum[mf][hh];
                v += __shfl_xor_sync(0xffffffffu, v, 1);
                v += __shfl_xor_sync(0xffffffffu, v, 2);
                l_state[mf][hh] = l_state[mf][hh] * cc[mf][hh] + v;
            }

        #pragma unroll
        for (int mf = 0; mf < 2; mf++)
            #pragma unroll
            for (int nf = 0; nf < 8; nf++) {
                acco[mf][nf][0] *= cc[mf][0];
                acco[mf][nf][1] *= cc[mf][0];
                acco[mf][nf][2] *= cc[mf][1];
                acco[mf][nf][3] *= cc[mf][1];
            }

        __syncwarp();   // P stores -> P fragment loads (warp-private rows)

        // ---- O += P V : warp tile 32q x 64d, contraction 32 keys ----
        #pragma unroll
        for (int ksi = 0; ksi < 4; ksi++) {
            const int kk = ksi * 8;
            uint32_t af[2][4];
            #pragma unroll
            for (int mf = 0; mf < 2; mf++) {
                int r = w * 32 + mf * 16 + lr;
                af[mf][0] = ps[r * PS_STR + kk + lc];
                af[mf][1] = ps[(r + 8) * PS_STR + kk + lc];
                af[mf][2] = ps[r * PS_STR + kk + lc + 4];
                af[mf][3] = ps[(r + 8) * PS_STR + kk + lc + 4];
            }
            uint32_t bf[8][2];
            #pragma unroll
            for (int nf = 0; nf < 8; nf++) {
                int n = nf * 8 + lr;
                bf[nf][0] = vs[(kk + lc) * FL_STR + n];
                bf[nf][1] = vs[(kk + lc + 4) * FL_STR + n];
            }
            #pragma unroll
            for (int mf = 0; mf < 2; mf++)
                #pragma unroll
                for (int nf = 0; nf < 8; nf++)
                    mma_tf32(acco[mf][nf], af[mf], bf[nf]);
        }
    }

    // ---- epilogue ----
    float* obase = O + ((size_t)(b * SS + q0)) * DD + h * HD;
    #pragma unroll
    for (int mf = 0; mf < 2; mf++) {
        float inv0 = 1.0f / l_state[mf][0];
        float inv1 = 1.0f / l_state[mf][1];
        int r = w * 32 + mf * 16 + lr;
        #pragma unroll
        for (int nf = 0; nf < 8; nf++) {
            int c = nf * 8 + 2 * lc;
            float2 v0 = { acco[mf][nf][0] * inv0, acco[mf][nf][1] * inv0 };
            float2 v1 = { acco[mf][nf][2] * inv1, acco[mf][nf][3] * inv1 };
            *(float2*)&obase[(size_t)r * DD + c] = v0;
            *(float2*)&obase[(size_t)(r + 8) * DD + c] = v1;
        }
    }
}

// ======================================================================
// launch
// ======================================================================
extern "C" void kernel_launch(void* const* d_in, const int* in_sizes, int n_in,
                              void* d_out, int out_size)
{
    const float* queries = (const float*)d_in[0];
    const float* keys    = (const float*)d_in[1];
    const float* values  = (const float*)d_in[2];
    const float* Wq      = (const float*)d_in[3];
    const float* Wk      = (const float*)d_in[4];
    const float* Wv      = (const float*)d_in[5];
    const float* Wo      = (const float*)d_in[6];
    const float* bo      = (const float*)d_in[7];
    float* out = (float*)d_out;

    float *gQ, *gK, *gV, *gA;
    cudaGetSymbolAddress((void**)&gQ, g_Q);
    cudaGetSymbolAddress((void**)&gK, g_K);
    cudaGetSymbolAddress((void**)&gV, g_V);
    cudaGetSymbolAddress((void**)&gA, g_att);

    cudaFuncSetAttribute(gemm_qkv,
                         cudaFuncAttributeMaxDynamicSharedMemorySize, G_SMEM_BYTES);
    cudaFuncSetAttribute(gemm_out,
                         cudaFuncAttributeMaxDynamicSharedMemorySize, G_SMEM_BYTES);
    cudaFuncSetAttribute(flash_tf32_v5,
                         cudaFuncAttributeMaxDynamicSharedMemorySize, FL_SMEM_BYTES);

    dim3 qkv_grid(4, 32, 3);   // 384 CTAs
    dim3 gemm_block(256);
    gemm_qkv<<<qkv_grid, gemm_block, G_SMEM_BYTES>>>(
        queries, keys, values, Wq, Wk, Wv, gQ, gK, gV);

    dim3 fl_grid(SS / 128, BB * HH);   // 512 CTAs
    flash_tf32_v5<<<fl_grid, 128, FL_SMEM_BYTES>>>(gQ, gK, gV, gA);

    dim3 out_grid(4, 32, 1);
    gemm_out<<<out_grid, gemm_block, G_SMEM_BYTES>>>(gA, Wo, bo, out);
}

// round 12
// speedup vs baseline: 1.1424x; 1.1424x over previous
#include <cuda_runtime.h>
#include <math.h>
#include <stdint.h>

#define BB 2
#define SS 2048
#define DD 1024
#define HH 16
#define HD 64

// -------- scratch (allocation-free: __device__ globals) --------
__device__ float g_Q[BB*SS*DD];
__device__ float g_K[BB*SS*DD];
__device__ float g_V[BB*SS*DD];
__device__ float g_att[BB*SS*DD];

// -------- helpers --------
__device__ __forceinline__ uint32_t f2tf32(float x) {
    uint32_t r;
    asm("cvt.rna.tf32.f32 %0, %1;" : "=r"(r) : "f"(x));
    return r;
}

__device__ __forceinline__ void mma_tf32(float* d, const uint32_t* a, const uint32_t* b) {
    asm volatile(
        "mma.sync.aligned.m16n8k8.row.col.f32.tf32.tf32.f32 "
        "{%0,%1,%2,%3},{%4,%5,%6,%7},{%8,%9},{%0,%1,%2,%3};"
        : "+f"(d[0]), "+f"(d[1]), "+f"(d[2]), "+f"(d[3])
        : "r"(a[0]), "r"(a[1]), "r"(a[2]), "r"(a[3]), "r"(b[0]), "r"(b[1]));
}

__device__ __forceinline__ void cp_async16(uint32_t smem_addr, const void* gptr) {
    asm volatile("cp.async.cg.shared.global [%0], [%1], 16;"
                 :: "r"(smem_addr), "l"(gptr));
}
__device__ __forceinline__ void cp_commit() {
    asm volatile("cp.async.commit_group;");
}
template <int N>
__device__ __forceinline__ void cp_wait() {
    asm volatile("cp.async.wait_group %0;" :: "n"(N));
}

// ======================================================================
// GEMM v6: C = A * Bw^T (+bias), tf32 mma.sync.
// block 128M x 128N, 256 threads (8 warps, 4Mx2N), warp tile 32x64, KT=32
// acc = 64 regs/thread -> 2 CTAs/SM (16 warps). 2-stage cp.async.
// smem: 2 x (128x36 + 128x36) floats = 73,728 B
// ======================================================================
#define G_SMEM_BYTES ((2*128*36 + 2*128*36) * 4)

__device__ __forceinline__ void gemm_body(
    const float* __restrict__ A, const float* __restrict__ Bw,
    const float* __restrict__ bias, float* __restrict__ C, int round_out)
{
    extern __shared__ float gsm[];
    float* As = gsm;                 // [2][128*36]
    float* Bs = gsm + 2 * 128 * 36;  // [2][128*36]

    const int tid  = threadIdx.x;
    const int lane = tid & 31;
    const int w    = tid >> 5;
    const int wm   = w & 3;        // 0..3 -> 32 rows each
    const int wn   = w >> 2;       // 0..1 -> 64 cols each
    const int lr   = lane >> 2;
    const int lc   = lane & 3;

    const int m0 = blockIdx.y * 128;
    const int n0 = blockIdx.x * 128;
    const int K = 1024, N = 1024;

    const uint32_t as_base = (uint32_t)__cvta_generic_to_shared(As);
    const uint32_t bs_base = (uint32_t)__cvta_generic_to_shared(Bs);

    // stage loader: A 128x32 + B 128x32 = 2048 float4 chunks, 256 thr x 8
    auto load_stage = [&](int s, int kt) {
        #pragma unroll
        for (int i = 0; i < 4; i++) {
            int id = tid + i * 256;
            int r = id >> 3, c = (id & 7) * 4;
            cp_async16(as_base + (s * 128 * 36 + r * 36 + c) * 4,
                       &A[(size_t)(m0 + r) * K + kt + c]);
            cp_async16(bs_base + (s * 128 * 36 + r * 36 + c) * 4,
                       &Bw[(size_t)(n0 + r) * K + kt + c]);
        }
        cp_commit();
    };

    float acc[2][8][4];
    #pragma unroll
    for (int i = 0; i < 2; i++)
        #pragma unroll
        for (int j = 0; j < 8; j++)
            #pragma unroll
            for (int t = 0; t < 4; t++) acc[i][j][t] = 0.0f;

    load_stage(0, 0);

    int st = 0;
    for (int kt = 0; kt < K; kt += 32, st ^= 1) {
        if (kt + 32 < K) { load_stage(st ^ 1, kt + 32); cp_wait<1>(); }
        else             { cp_wait<0>(); }
        __syncthreads();

        const float* Ac = As + st * 128 * 36;
        const float* Bc = Bs + st * 128 * 36;

        #pragma unroll
        for (int ks = 0; ks < 4; ks++) {
            const int kk = ks * 8;
            uint32_t af[2][4];
            #pragma unroll
            for (int mf = 0; mf < 2; mf++) {
                int r = wm * 32 + mf * 16 + lr;
                af[mf][0] = f2tf32(Ac[r * 36 + kk + lc]);
                af[mf][1] = f2tf32(Ac[(r + 8) * 36 + kk + lc]);
                af[mf][2] = f2tf32(Ac[r * 36 + kk + lc + 4]);
                af[mf][3] = f2tf32(Ac[(r + 8) * 36 + kk + lc + 4]);
            }
            uint32_t bf[8][2];
            #pragma unroll
            for (int nf = 0; nf < 8; nf++) {
                int n = wn * 64 + nf * 8 + lr;
                bf[nf][0] = f2tf32(Bc[n * 36 + kk + lc]);
                bf[nf][1] = f2tf32(Bc[n * 36 + kk + lc + 4]);
            }
            #pragma unroll
            for (int mf = 0; mf < 2; mf++)
                #pragma unroll
                for (int nf = 0; nf < 8; nf++)
                    mma_tf32(acc[mf][nf], af[mf], bf[nf]);
        }
        __syncthreads();
    }

    #pragma unroll
    for (int mf = 0; mf < 2; mf++) {
        int r = m0 + wm * 32 + mf * 16 + lr;
        #pragma unroll
        for (int nf = 0; nf < 8; nf++) {
            int c = n0 + wn * 64 + nf * 8 + 2 * lc;
            float b0 = 0.0f, b1 = 0.0f;
            if (bias) { b0 = bias[c]; b1 = bias[c + 1]; }
            float o00 = acc[mf][nf][0] + b0, o01 = acc[mf][nf][1] + b1;
            float o10 = acc[mf][nf][2] + b0, o11 = acc[mf][nf][3] + b1;
            if (round_out) {
                o00 = __uint_as_float(f2tf32(o00)); o01 = __uint_as_float(f2tf32(o01));
                o10 = __uint_as_float(f2tf32(o10)); o11 = __uint_as_float(f2tf32(o11));
            }
            float2 v0 = { o00, o01 };
            float2 v1 = { o10, o11 };
            *(float2*)&C[(size_t)r * N + c] = v0;
            *(float2*)&C[(size_t)(r + 8) * N + c] = v1;
        }
    }
}

__global__ __launch_bounds__(256, 2) void gemm_qkv(
    const float* __restrict__ Xq, const float* __restrict__ Xk,
    const float* __restrict__ Xv,
    const float* __restrict__ Wq, const float* __restrict__ Wk,
    const float* __restrict__ Wv,
    float* __restrict__ Oq, float* __restrict__ Ok, float* __restrict__ Ov)
{
    const int z = blockIdx.z;
    const float* A  = (z == 0) ? Xq : (z == 1) ? Xk : Xv;
    const float* Bw = (z == 0) ? Wq : (z == 1) ? Wk : Wv;
    float*       C  = (z == 0) ? Oq : (z == 1) ? Ok : Ov;
    gemm_body(A, Bw, nullptr, C, 1);
}

__global__ __launch_bounds__(256, 2) void gemm_out(
    const float* __restrict__ A, const float* __restrict__ Bw,
    const float* __restrict__ bias, float* __restrict__ C)
{
    gemm_body(A, Bw, bias, C, 0);
}

// ======================================================================
// Flash attention v4 (R9-proven, ~275us): 128-q tile, 4 warps (32q each),
// 64-key tiles, register prefetch of next K/V tile, warp-local softmax.
// smem stride 68; inputs pre-rounded tf32 by gemm epilogue -> no cvt.
// layout (floats): qs 128x68 @0, ks 64x68 @8704, vs @13056, ps 128x68 @17408
// total 26112 floats = 104,448 B
// ======================================================================
#define FL_STR 68
#define FL_SMEM_BYTES (26112 * 4)

__global__ __launch_bounds__(128) void flash_tf32_v4(
    const float* __restrict__ Q, const float* __restrict__ Kp,
    const float* __restrict__ Vp, float* __restrict__ O)
{
    extern __shared__ float smf[];
    uint32_t* qs = (uint32_t*)smf;
    uint32_t* ks = (uint32_t*)(smf + 8704);
    uint32_t* vs = (uint32_t*)(smf + 13056);
    uint32_t* ps = (uint32_t*)(smf + 17408);

    const int tid  = threadIdx.x;
    const int lane = tid & 31;
    const int w    = tid >> 5;
    const int lr   = lane >> 2;
    const int lc   = lane & 3;

    const int bh = blockIdx.y;
    const int b  = bh >> 4;
    const int h  = bh & 15;
    const int q0 = blockIdx.x * 128;
    const float scale = 0.03125f;   // 2^-5 exact

    const int fr = tid >> 4;
    const int fc = (tid & 15) * 4;

    const float* qbase = Q + ((size_t)(b * SS + q0)) * DD + h * HD;
    #pragma unroll
    for (int i = 0; i < 16; i++) {
        int r = fr + i * 8;
        float4 v = *(const float4*)&qbase[(size_t)r * DD + fc];
        uint4 u = { __float_as_uint(v.x * scale), __float_as_uint(v.y * scale),
                    __float_as_uint(v.z * scale), __float_as_uint(v.w * scale) };
        *(uint4*)&qs[r * FL_STR + fc] = u;
    }

    float m_state[2][2], l_state[2][2];
    float acco[2][8][4];
    #pragma unroll
    for (int mf = 0; mf < 2; mf++)
        #pragma unroll
        for (int hh = 0; hh < 2; hh++) { m_state[mf][hh] = -INFINITY; l_state[mf][hh] = 0.0f; }
    #pragma unroll
    for (int mf = 0; mf < 2; mf++)
        #pragma unroll
        for (int nf = 0; nf < 8; nf++)
            #pragma unroll
            for (int t = 0; t < 4; t++) acco[mf][nf][t] = 0.0f;

    const float* kb0 = Kp + ((size_t)(b * SS)) * DD + h * HD;
    const float* vb0 = Vp + ((size_t)(b * SS)) * DD + h * HD;
    float4 kreg[8], vreg[8];
    #pragma unroll
    for (int i = 0; i < 8; i++) {
        int r = fr + i * 8;
        kreg[i] = *(const float4*)&kb0[(size_t)r * DD + fc];
        vreg[i] = *(const float4*)&vb0[(size_t)r * DD + fc];
    }

    for (int kb = 0; kb < SS / 64; kb++) {
        __syncthreads();
        #pragma unroll
        for (int i = 0; i < 8; i++) {
            int r = fr + i * 8;
            uint4 uk = { __float_as_uint(kreg[i].x), __float_as_uint(kreg[i].y),
                         __float_as_uint(kreg[i].z), __float_as_uint(kreg[i].w) };
            uint4 uv = { __float_as_uint(vreg[i].x), __float_as_uint(vreg[i].y),
                         __float_as_uint(vreg[i].z), __float_as_uint(vreg[i].w) };
            *(uint4*)&ks[r * FL_STR + fc] = uk;
            *(uint4*)&vs[r * FL_STR + fc] = uv;
        }
        __syncthreads();

        if (kb + 1 < SS / 64) {
            const float* kbn = Kp + ((size_t)(b * SS + (kb + 1) * 64)) * DD + h * HD;
            const float* vbn = Vp + ((size_t)(b * SS + (kb + 1) * 64)) * DD + h * HD;
            #pragma unroll
            for (int i = 0; i < 8; i++) {
                int r = fr + i * 8;
                kreg[i] = *(const float4*)&kbn[(size_t)r * DD + fc];
                vreg[i] = *(const float4*)&vbn[(size_t)r * DD + fc];
            }
        }

        float accs[2][8][4];
        #pragma unroll
        for (int mf = 0; mf < 2; mf++)
            #pragma unroll
            for (int nf = 0; nf < 8; nf++)
                #pragma unroll
                for (int t = 0; t < 4; t++) accs[mf][nf][t] = 0.0f;

        #pragma unroll
        for (int ksi = 0; ksi < 8; ksi++) {
            const int kk = ksi * 8;
            uint32_t af[2][4];
            #pragma unroll
            for (int mf = 0; mf < 2; mf++) {
                int r = w * 32 + mf * 16 + lr;
                af[mf][0] = qs[r * FL_STR + kk + lc];
                af[mf][1] = qs[(r + 8) * FL_STR + kk + lc];
                af[mf][2] = qs[r * FL_STR + kk + lc + 4];
                af[mf][3] = qs[(r + 8) * FL_STR + kk + lc + 4];
            }
            uint32_t bf[8][2];
            #pragma unroll
            for (int nf = 0; nf < 8; nf++) {
                int n = nf * 8 + lr;
                bf[nf][0] = ks[n * FL_STR + kk + lc];
                bf[nf][1] = ks[n * FL_STR + kk + lc + 4];
            }
            #pragma unroll
            for (int mf = 0; mf < 2; mf++)
                #pragma unroll
                for (int nf = 0; nf < 8; nf++)
                    mma_tf32(accs[mf][nf], af[mf], bf[nf]);
        }

        float cc[2][2];
        #pragma unroll
        for (int mf = 0; mf < 2; mf++)
            #pragma unroll
            for (int hh = 0; hh < 2; hh++) {
                float v = -INFINITY;
                #pragma unroll
                for (int nf = 0; nf < 8; nf++) {
                    v = fmaxf(v, accs[mf][nf][2 * hh]);
                    v = fmaxf(v, accs[mf][nf][2 * hh + 1]);
                }
                v = fmaxf(v, __shfl_xor_sync(0xffffffffu, v, 1));
                v = fmaxf(v, __shfl_xor_sync(0xffffffffu, v, 2));
                float mnew = fmaxf(m_state[mf][hh], v);
                cc[mf][hh] = __expf(m_state[mf][hh] - mnew);
                m_state[mf][hh] = mnew;
            }

        float rsum[2][2] = {};
        #pragma unroll
        for (int mf = 0; mf < 2; mf++) {
            #pragma unroll
            for (int nf = 0; nf < 8; nf++) {
                float p0 = __expf(accs[mf][nf][0] - m_state[mf][0]);
                float p1 = __expf(accs[mf][nf][1] - m_state[mf][0]);
                float p2 = __expf(accs[mf][nf][2] - m_state[mf][1]);
                float p3 = __expf(accs[mf][nf][3] - m_state[mf][1]);
                rsum[mf][0] += p0 + p1;
                rsum[mf][1] += p2 + p3;
                int r = w * 32 + mf * 16 + lr;
                int c = nf * 8 + 2 * lc;
                uint2 u0 = { f2tf32(p0), f2tf32(p1) };
                uint2 u1 = { f2tf32(p2), f2tf32(p3) };
                *(uint2*)&ps[r * FL_STR + c] = u0;
                *(uint2*)&ps[(r + 8) * FL_STR + c] = u1;
            }
        }
        #pragma unroll
        for (int mf = 0; mf < 2; mf++)
            #pragma unroll
            for (int hh = 0; hh < 2; hh++) {
                float v = rsum[mf][hh];
                v += __shfl_xor_sync(0xffffffffu, v, 1);
                v += __shfl_xor_sync(0xffffffffu, v, 2);
                l_state[mf][hh] = l_state[mf][hh] * cc[mf][hh] + v;
            }

        #pragma unroll
        for (int mf = 0; mf < 2; mf++)
            #pragma unroll
            for (int nf = 0; nf < 8; nf++) {
                acco[mf][nf][0] *= cc[mf][0];
                acco[mf][nf][1] *= cc[mf][0];
                acco[mf][nf][2] *= cc[mf][1];
                acco[mf][nf][3] *= cc[mf][1];
            }

        __syncwarp();

        #pragma unroll
        for (int ksi = 0; ksi < 8; ksi++) {
            const int kk = ksi * 8;
            uint32_t af[2][4];
            #pragma unroll
            for (int mf = 0; mf < 2; mf++) {
                int r = w * 32 + mf * 16 + lr;
                af[mf][0] = ps[r * FL_STR + kk + lc];
                af[mf][1] = ps[(r + 8) * FL_STR + kk + lc];
                af[mf][2] = ps[r * FL_STR + kk + lc + 4];
                af[mf][3] = ps[(r + 8) * FL_STR + kk + lc + 4];
            }
            uint32_t bf[8][2];
            #pragma unroll
            for (int nf = 0; nf < 8; nf++) {
                int n = nf * 8 + lr;
                bf[nf][0] = vs[(kk + lc) * FL_STR + n];
                bf[nf][1] = vs[(kk + lc + 4) * FL_STR + n];
            }
            #pragma unroll
            for (int mf = 0; mf < 2; mf++)
                #pragma unroll
                for (int nf = 0; nf < 8; nf++)
                    mma_tf32(acco[mf][nf], af[mf], bf[nf]);
        }
    }

    float* obase = O + ((size_t)(b * SS + q0)) * DD + h * HD;
    #pragma unroll
    for (int mf = 0; mf < 2; mf++) {
        float inv0 = 1.0f / l_state[mf][0];
        float inv1 = 1.0f / l_state[mf][1];
        int r = w * 32 + mf * 16 + lr;
        #pragma unroll
        for (int nf = 0; nf < 8; nf++) {
            int c = nf * 8 + 2 * lc;
            float2 v0 = { acco[mf][nf][0] * inv0, acco[mf][nf][1] * inv0 };
            float2 v1 = { acco[mf][nf][2] * inv1, acco[mf][nf][3] * inv1 };
            *(float2*)&obase[(size_t)r * DD + c] = v0;
            *(float2*)&obase[(size_t)(r + 8) * DD + c] = v1;
        }
    }
}

// ======================================================================
// launch
// ======================================================================
extern "C" void kernel_launch(void* const* d_in, const int* in_sizes, int n_in,
                              void* d_out, int out_size)
{
    const float* queries = (const float*)d_in[0];
    const float* keys    = (const float*)d_in[1];
    const float* values  = (const float*)d_in[2];
    const float* Wq      = (const float*)d_in[3];
    const float* Wk      = (const float*)d_in[4];
    const float* Wv      = (const float*)d_in[5];
    const float* Wo      = (const float*)d_in[6];
    const float* bo      = (const float*)d_in[7];
    float* out = (float*)d_out;

    float *gQ, *gK, *gV, *gA;
    cudaGetSymbolAddress((void**)&gQ, g_Q);
    cudaGetSymbolAddress((void**)&gK, g_K);
    cudaGetSymbolAddress((void**)&gV, g_V);
    cudaGetSymbolAddress((void**)&gA, g_att);

    cudaFuncSetAttribute(gemm_qkv,
                         cudaFuncAttributeMaxDynamicSharedMemorySize, G_SMEM_BYTES);
    cudaFuncSetAttribute(gemm_out,
                         cudaFuncAttributeMaxDynamicSharedMemorySize, G_SMEM_BYTES);
    cudaFuncSetAttribute(flash_tf32_v4,
                         cudaFuncAttributeMaxDynamicSharedMemorySize, FL_SMEM_BYTES);

    dim3 qkv_grid(8, 32, 3);   // 768 CTAs (128x128 tiles)
    dim3 gemm_block(256);
    gemm_qkv<<<qkv_grid, gemm_block, G_SMEM_BYTES>>>(
        queries, keys, values, Wq, Wk, Wv, gQ, gK, gV);

    dim3 fl_grid(SS / 128, BB * HH);   // 512 CTAs
    flash_tf32_v4<<<fl_grid, 128, FL_SMEM_BYTES>>>(gQ, gK, gV, gA);

    dim3 out_grid(8, 32, 1);
    gemm_out<<<out_grid, gemm_block, G_SMEM_BYTES>>>(gA, Wo, bo, out);
}